// round 1
// baseline (speedup 1.0000x reference)
#include <cuda_runtime.h>

#define Nn 100000
#define Mm 800000
#define FIN 64
#define FE  16
#define HH  64

// Scratch (device globals; no allocations allowed)
__device__ float4 g_h2[Nn * 16];       // h2[N][64] as float4 rows
__device__ float4 g_aggE[Nn * 12];     // aggregated edge_feat [N][3][16]
__device__ float  g_cntE[Nn * 3];      // per (dst, edge_type) counts

__device__ __forceinline__ void red_add_f4(float4* p, float4 v) {
    asm volatile("red.global.add.v4.f32 [%0], {%1,%2,%3,%4};"
                 :: "l"(p), "f"(v.x), "f"(v.y), "f"(v.z), "f"(v.w)
                 : "memory");
}

__global__ void zero_kernel() {
    int gid = blockIdx.x * blockDim.x + threadIdx.x;
    int stride = gridDim.x * blockDim.x;
    float4 z = make_float4(0.f, 0.f, 0.f, 0.f);
    for (int i = gid; i < Nn * 12; i += stride) g_aggE[i] = z;
    for (int i = gid; i < Nn * 3; i += stride) g_cntE[i] = 0.f;
}

// 4 threads per edge: scatter-add edge_feat[e] (16 floats) into aggE[dst][etype]
__global__ void edge_scatter_kernel(const float* __restrict__ ef,
                                    const int* __restrict__ edst,
                                    const int* __restrict__ etype) {
    int gid = blockIdx.x * blockDim.x + threadIdx.x;
    int e = gid >> 2, q = gid & 3;
    if (e >= Mm) return;
    int dst = edst[e];
    int t   = etype[e];
    float4 v = ((const float4*)ef)[e * 4 + q];
    red_add_f4(&g_aggE[dst * 12 + t * 4 + q], v);
    if (q == 0) atomicAdd(&g_cntE[dst * 3 + t], 1.0f);
}

// Per-node dual projection: out = h1 = x@W1[t]+b1 ; g_h2 = x@W2[t]+b2
// Block: 256 threads; 64-node tiles; thread = (node-group of 4) x (4 columns).
// Both node-type weight rows loaded once per k; per-node FSEL picks the type.
__global__ __launch_bounds__(256, 2)
void node_kernel(const float* __restrict__ x, const int* __restrict__ ntype,
                 const float* __restrict__ W1, const float* __restrict__ b1,
                 const float* __restrict__ W2, const float* __restrict__ b2,
                 float* __restrict__ out) {
    extern __shared__ float sm[];
    float* W1s = sm;              // 8192 : [2][64][64]
    float* W2s = sm + 8192;       // 8192
    float* b1s = sm + 16384;      // 128
    float* b2s = sm + 16512;      // 128
    float* xs  = sm + 16640;      // [64][68] padded x tile
    int tid = threadIdx.x;

    for (int i = tid; i < 8192; i += 256) { W1s[i] = W1[i]; W2s[i] = W2[i]; }
    if (tid < 128) { b1s[tid] = b1[tid]; b2s[tid] = b2[tid]; }
    __syncthreads();

    const int cg = tid & 15, c0 = cg * 4;
    const int n0 = (tid >> 4) * 4;
    const float4 b1a = *(const float4*)&b1s[c0];
    const float4 b1b = *(const float4*)&b1s[64 + c0];
    const float4 b2a = *(const float4*)&b2s[c0];
    const float4 b2b = *(const float4*)&b2s[64 + c0];

    const int ntiles = (Nn + 63) / 64;
    for (int tile = blockIdx.x; tile < ntiles; tile += gridDim.x) {
        int base = tile * 64;
        __syncthreads();   // protect xs from previous iteration's readers
        for (int i = tid; i < 64 * 16; i += 256) {
            int n = i >> 4, kq = i & 15;
            int node = base + n;
            float4 v = make_float4(0.f, 0.f, 0.f, 0.f);
            if (node < Nn) v = ((const float4*)x)[node * 16 + kq];
            *(float4*)&xs[n * 68 + kq * 4] = v;
        }
        __syncthreads();

        bool pt[4];
        #pragma unroll
        for (int j = 0; j < 4; j++) {
            int node = base + n0 + j;
            pt[j] = (node < Nn) ? (ntype[node] != 0) : false;
        }
        float4 acc1[4], acc2[4];
        #pragma unroll
        for (int j = 0; j < 4; j++) {
            acc1[j] = pt[j] ? b1b : b1a;
            acc2[j] = pt[j] ? b2b : b2a;
        }

        #pragma unroll 4
        for (int k = 0; k < 64; k++) {
            float4 w1a = *(const float4*)&W1s[k * 64 + c0];
            float4 w1b = *(const float4*)&W1s[4096 + k * 64 + c0];
            float4 w2a = *(const float4*)&W2s[k * 64 + c0];
            float4 w2b = *(const float4*)&W2s[4096 + k * 64 + c0];
            #pragma unroll
            for (int j = 0; j < 4; j++) {
                float xv = xs[(n0 + j) * 68 + k];
                float4 w1 = pt[j] ? w1b : w1a;
                float4 w2 = pt[j] ? w2b : w2a;
                acc1[j].x += xv * w1.x; acc1[j].y += xv * w1.y;
                acc1[j].z += xv * w1.z; acc1[j].w += xv * w1.w;
                acc2[j].x += xv * w2.x; acc2[j].y += xv * w2.y;
                acc2[j].z += xv * w2.z; acc2[j].w += xv * w2.w;
            }
        }

        #pragma unroll
        for (int j = 0; j < 4; j++) {
            int node = base + n0 + j;
            if (node < Nn) {
                ((float4*)out)[node * 16 + cg] = acc1[j];
                g_h2[node * 16 + cg] = acc2[j];
            }
        }
    }
}

// 16 threads per edge: out[dst] += h2[src]  (64 floats = 16 x red.v4)
__global__ void h2_scatter_kernel(const int* __restrict__ esrc,
                                  const int* __restrict__ edst,
                                  float4* __restrict__ out) {
    int gid = blockIdx.x * blockDim.x + threadIdx.x;
    int e = gid >> 4, q = gid & 15;
    if (e >= Mm) return;
    int src = esrc[e];
    int dst = edst[e];
    float4 v = g_h2[src * 16 + q];
    red_add_f4(&out[dst * 16 + q], v);
}

// out[i] += sum_t aggE[i][t] @ W5[t] + cntE[i][t] * b5[t]
__global__ __launch_bounds__(256)
void agg_gemm_kernel(const float* __restrict__ W5, const float* __restrict__ b5,
                     float* __restrict__ out) {
    __shared__ __align__(16) float W5s[3072];   // [3][16][64]
    __shared__ __align__(16) float b5s[192];
    __shared__ __align__(16) float as[64 * 52]; // padded aggE tile [64][48]
    __shared__ __align__(16) float cs[64 * 4];
    int tid = threadIdx.x;
    for (int i = tid; i < 3072; i += 256) W5s[i] = W5[i];
    if (tid < 192) b5s[tid] = b5[tid];
    __syncthreads();

    const int cg = tid & 15, c0 = cg * 4;
    const int n0 = (tid >> 4) * 4;
    const int ntiles = (Nn + 63) / 64;
    for (int tile = blockIdx.x; tile < ntiles; tile += gridDim.x) {
        int base = tile * 64;
        __syncthreads();
        for (int i = tid; i < 64 * 12; i += 256) {
            int n = i / 12, q = i % 12;
            int node = base + n;
            float4 v = make_float4(0.f, 0.f, 0.f, 0.f);
            if (node < Nn) v = g_aggE[node * 12 + q];
            *(float4*)&as[n * 52 + q * 4] = v;
        }
        for (int i = tid; i < 64 * 3; i += 256) {
            int n = i / 3, t = i % 3;
            int node = base + n;
            cs[n * 4 + t] = (node < Nn) ? g_cntE[node * 3 + t] : 0.f;
        }
        __syncthreads();

        float4 acc[4];
        #pragma unroll
        for (int j = 0; j < 4; j++) acc[j] = make_float4(0.f, 0.f, 0.f, 0.f);

        #pragma unroll 4
        for (int tk = 0; tk < 48; tk++) {   // tk = t*16 + k
            float4 w = *(const float4*)&W5s[tk * 64 + c0];
            #pragma unroll
            for (int j = 0; j < 4; j++) {
                float av = as[(n0 + j) * 52 + tk];
                acc[j].x += av * w.x; acc[j].y += av * w.y;
                acc[j].z += av * w.z; acc[j].w += av * w.w;
            }
        }
        #pragma unroll
        for (int t = 0; t < 3; t++) {
            float4 bv = *(const float4*)&b5s[t * 64 + c0];
            #pragma unroll
            for (int j = 0; j < 4; j++) {
                float cv = cs[(n0 + j) * 4 + t];
                acc[j].x += cv * bv.x; acc[j].y += cv * bv.y;
                acc[j].z += cv * bv.z; acc[j].w += cv * bv.w;
            }
        }
        #pragma unroll
        for (int j = 0; j < 4; j++) {
            int node = base + n0 + j;
            if (node < Nn) {
                float4 o = ((float4*)out)[node * 16 + cg];
                o.x += acc[j].x; o.y += acc[j].y;
                o.z += acc[j].z; o.w += acc[j].w;
                ((float4*)out)[node * 16 + cg] = o;
            }
        }
    }
}

extern "C" void kernel_launch(void* const* d_in, const int* in_sizes, int n_in,
                              void* d_out, int out_size) {
    const float *x = nullptr, *ef = nullptr;
    const float *W[4] = {nullptr, nullptr, nullptr, nullptr};
    const float *B[4] = {nullptr, nullptr, nullptr, nullptr};
    const float *W5 = nullptr, *b5 = nullptr;
    const int *ntype = nullptr, *esrc = nullptr, *edst = nullptr, *etype = nullptr;
    int wI = 0, bI = 0, mI = 0;
    for (int i = 0; i < n_in; i++) {
        long s = in_sizes[i];
        const void* p = d_in[i];
        if (s == (long)Nn * FIN)      x = (const float*)p;
        else if (s == (long)Mm * FE)  ef = (const float*)p;
        else if (s == Nn)             ntype = (const int*)p;
        else if (s == Mm) {
            if (mI == 0) esrc = (const int*)p;
            else if (mI == 1) edst = (const int*)p;
            else etype = (const int*)p;
            mI++;
        }
        else if (s == 2 * FIN * HH) { if (wI < 4) W[wI++] = (const float*)p; }
        else if (s == 2 * HH)       { if (bI < 4) B[bI++] = (const float*)p; }
        else if (s == 3 * FE * HH)  W5 = (const float*)p;
        else if (s == 3 * HH)       b5 = (const float*)p;
    }
    float* out = (float*)d_out;

    cudaFuncSetAttribute(node_kernel, cudaFuncAttributeMaxDynamicSharedMemorySize, 84 * 1024);

    zero_kernel<<<1024, 256>>>();
    edge_scatter_kernel<<<(Mm * 4 + 255) / 256, 256>>>(ef, edst, etype);
    node_kernel<<<296, 256, 83968>>>(x, ntype, W[0], B[0], W[1], B[1], out);
    h2_scatter_kernel<<<(Mm * 16 + 255) / 256, 256>>>(esrc, edst, (float4*)out);
    agg_gemm_kernel<<<592, 256>>>(W5, b5, out);
}